// round 3
// baseline (speedup 1.0000x reference)
#include <cuda_runtime.h>

#define NMAX 4194304
#define CN 10

// ---------------- device globals --------------------------------------------
struct GAcc {
    double   ce, fo;
    unsigned umaxb, uminneg;   // max(unc bits), max(~unc bits)  (zero-init neutral)
    unsigned ticket, pad;
    double   hist[88];         // [(b*2+acc)*2 + {0:wc,1:wu}], b in [0,21]
};
static __device__ GAcc g;                         // zero at load; self-reset by finalizer
static __device__ __align__(16) float g_rec[NMAX]; // unc with sign bit = !acc

// ---------------- fast math (FFMA-only, no MUFU) ----------------------------
__device__ __forceinline__ float fast_logf(float a) {
    int   e = (__float_as_int(a) - 0x3f2aaaab) & 0xff800000;
    float m = __int_as_float(__float_as_int(a) - e);
    float i = (float)e * 1.19209290e-7f;
    float f = m - 1.0f;
    float s = f * f;
    float r = fmaf(0.230836749f, f, -0.279208571f);
    float t = fmaf(0.331826031f, f, -0.498910338f);
    r = fmaf(r, s, t);
    r = fmaf(r, s, f);
    r = fmaf(i, 0.693147182f, r);
    return r;
}

__device__ __forceinline__ float fast_expf(float a) {
    float j  = fmaf(1.442695041f, a, 12582912.0f);
    int   ji = __float_as_int(j) - 0x4B400000;
    j = j - 12582912.0f;
    float f = fmaf(j, -0.693145752f, a);
    f = fmaf(j, -1.42860677e-6f, f);
    float r = 1.37805939e-3f;
    r = fmaf(r, f, 8.37312452e-3f);
    r = fmaf(r, f, 4.16695364e-2f);
    r = fmaf(r, f, 1.66665524e-1f);
    r = fmaf(r, f, 4.99999851e-1f);
    r = fmaf(r, f, 1.00000000e+0f);
    r = fmaf(r, f, 1.00000000e+0f);
    return __int_as_float(__float_as_int(r) + (ji << 23));
}

__device__ __forceinline__ float fast_rcp(float x) {   // x > 0, normal; FFMA-only
    float r = __int_as_float(0x7EF311C3 - __float_as_int(x));
    r = r * fmaf(-x, r, 2.0f);
    r = r * fmaf(-x, r, 2.0f);
    r = r * fmaf(-x, r, 2.0f);
    return r;
}

// ---------------- pass 1: smem-staged coalesced reads -----------------------
#define P1_T     256
#define CH_PAIRS 256          // pairs (2 samples) per chunk = P1_T
#define CH_F4    (CH_PAIRS * 5)

__device__ __forceinline__ float proc_sample(const float* p, const float* yy, int label,
                                             float& ceS, float& foS, float& umn, float& umx) {
    float ent = 0.0f, A = 0.0f, B = 0.0f;
    float best = p[0]; int arg = 0;
    #pragma unroll
    for (int c = 0; c < CN; c++) {
        float pk  = p[c];
        float lpe = fast_logf(fmaxf(pk, 1e-10f));             // EPS clamp (entropy)
        float lpf = (pk >= 1e-8f) ? lpe : -18.420680744f;     // FOCAL_EPS clamp
        ent = fmaf(pk, lpe, ent);
        float yl = yy[c] * lpf;
        A += yl;
        B = fmaf(yl, pk, B);
        if (c > 0 && pk > best) { best = pk; arg = c; }       // first-occurrence argmax
    }
    float unc = fmaxf(-ent, 0.0f);
    ceS += -A;
    foS += (B - A);
    umn = fminf(umn, unc);
    umx = fmaxf(umx, unc);
    int acc = (arg == label);
    return __int_as_float(__float_as_int(unc) | (acc ? 0 : 0x80000000));
}

__global__ void __launch_bounds__(P1_T) pass1(const float* __restrict__ in0,
                                              const float* __restrict__ in1, int n) {
    __shared__ float4 sP[CH_F4];
    __shared__ float4 sY[CH_F4];
    __shared__ int s_label, s_swap;
    __shared__ float rC[P1_T / 32], rF[P1_T / 32], rMn[P1_T / 32], rMx[P1_T / 32];

    if (threadIdx.x == 0) {
        bool onehot = true;
        #pragma unroll
        for (int c = 0; c < CN; c++) { float v = in1[c]; if (v != 0.0f && v != 1.0f) onehot = false; }
        const float* Y = onehot ? in1 : in0;
        s_swap = onehot ? 0 : 1;
        float best = Y[0]; int arg = 0;
        #pragma unroll
        for (int c = 1; c < CN; c++) { float v = Y[c]; if (v > best) { best = v; arg = c; } }
        s_label = arg;
    }
    __syncthreads();
    const int swap = s_swap;
    const int label = s_label;
    const float4* P4 = reinterpret_cast<const float4*>(swap ? in1 : in0);
    const float4* Y4 = reinterpret_cast<const float4*>(swap ? in0 : in1);

    float ceS = 0.0f, foS = 0.0f;
    float umn = 3.402823466e38f, umx = 0.0f;

    const int npair  = n >> 1;
    const int nF4    = npair * 5;
    const int nchunk = (npair + CH_PAIRS - 1) / CH_PAIRS;

    #pragma unroll 1
    for (int c = blockIdx.x; c < nchunk; c += gridDim.x) {
        int f4base = c * CH_F4;
        #pragma unroll
        for (int r = 0; r < 5; r++) {
            int idx = f4base + r * P1_T + threadIdx.x;
            float4 v = make_float4(0.f, 0.f, 0.f, 0.f);
            float4 w = v;
            if (idx < nF4) { v = __ldcs(P4 + idx); w = __ldcs(Y4 + idx); }
            sP[r * P1_T + threadIdx.x] = v;
            sY[r * P1_T + threadIdx.x] = w;
        }
        __syncthreads();
        int pr = c * CH_PAIRS + threadIdx.x;
        if (pr < npair) {
            float p[20], y[20];
            #pragma unroll
            for (int j = 0; j < 5; j++) {
                float4 a = sP[threadIdx.x * 5 + j];
                float4 b = sY[threadIdx.x * 5 + j];
                p[4 * j] = a.x; p[4 * j + 1] = a.y; p[4 * j + 2] = a.z; p[4 * j + 3] = a.w;
                y[4 * j] = b.x; y[4 * j + 1] = b.y; y[4 * j + 2] = b.z; y[4 * j + 3] = b.w;
            }
            float r0 = proc_sample(p,      y,      label, ceS, foS, umn, umx);
            float r1 = proc_sample(p + 10, y + 10, label, ceS, foS, umn, umx);
            reinterpret_cast<float2*>(g_rec)[pr] = make_float2(r0, r1);
        }
        __syncthreads();
    }

    // odd-n tail
    if ((n & 1) && blockIdx.x == 0 && threadIdx.x == 0) {
        int i = n - 1;
        const float* P = swap ? in1 : in0;
        const float* Y = swap ? in0 : in1;
        float v[CN], w[CN];
        #pragma unroll
        for (int c = 0; c < CN; c++) { v[c] = P[(size_t)i * CN + c]; w[c] = Y[(size_t)i * CN + c]; }
        g_rec[i] = proc_sample(v, w, label, ceS, foS, umn, umx);
    }

    #pragma unroll
    for (int o = 16; o; o >>= 1) {
        ceS += __shfl_xor_sync(0xffffffffu, ceS, o);
        foS += __shfl_xor_sync(0xffffffffu, foS, o);
        umn = fminf(umn, __shfl_xor_sync(0xffffffffu, umn, o));
        umx = fmaxf(umx, __shfl_xor_sync(0xffffffffu, umx, o));
    }
    int wid = threadIdx.x >> 5, lid = threadIdx.x & 31;
    if (lid == 0) { rC[wid] = ceS; rF[wid] = foS; rMn[wid] = umn; rMx[wid] = umx; }
    __syncthreads();
    if (threadIdx.x == 0) {
        float cc = rC[0], f = rF[0], mn = rMn[0], mx = rMx[0];
        #pragma unroll
        for (int q = 1; q < P1_T / 32; q++) {
            cc += rC[q]; f += rF[q]; mn = fminf(mn, rMn[q]); mx = fmaxf(mx, rMx[q]);
        }
        atomicAdd(&g.ce, (double)cc);
        atomicAdd(&g.fo, (double)f);
        atomicMax(&g.umaxb, __float_as_uint(mx));
        atomicMax(&g.uminneg, ~__float_as_uint(mn));
    }
}

// ---------------- pass 2: weight recompute + binning + finalize -------------
#define P2_T 128
#define P2_S 89
#define P2_GRID 592

__device__ __forceinline__ void hist_one(float* base, float rec, const float* th) {
    int   bits = __float_as_int(rec);
    int   acc  = (bits < 0) ? 0 : 1;
    float unc  = fabsf(rec);

    // soft_T(e), temp=0.01: hard step, compare-based short circuit
    float e   = unc * 0.43429448190325176f;                  // unc / ln(10)
    float num = e * 0.9f;
    float den = fmaxf((1.0f - e) * 0.1f, 1e-10f);
    float s;
    if (num >= 1.18546522f * den) {           // x >= 17 -> sigmoid rounds to 1.0f
        s = 1.0f;
    } else if (num <= 0.77880078f * den) {    // x <= -25 -> contribution < 1.4e-11
        s = 0.0f;
    } else {
        float x = 100.0f * (fast_logf(fmaxf(num, 1e-37f)) - fast_logf(den));
        s = fast_rcp(1.0f + fast_expf(-x));
    }
    float em = fast_expf(-2.0f * unc);
    float t  = (1.0f - em) * fast_rcp(1.0f + em);            // tanh(unc), no MUFU

    float wc = (1.0f - s) * (1.0f - t);
    float wu = s * t;
    int b = 0;
    #pragma unroll
    for (int j = 0; j < 21; j++) b += (unc > th[j]) ? 1 : 0;
    int key = (b * 2 + acc) * 2;
    base[key]     += wc;
    base[key + 1] += wu;
}

__global__ void __launch_bounds__(P2_T) pass2(int n, float* __restrict__ out) {
    __shared__ float sh[P2_T * P2_S];
    float* base = sh + threadIdx.x * P2_S;
    #pragma unroll
    for (int k = 0; k < P2_S; k++) base[k] = 0.0f;
    __syncthreads();

    float umin  = __uint_as_float(~g.uminneg);
    float umax  = __uint_as_float(g.umaxb);
    float range = umax - umin;
    float th[21];
    #pragma unroll
    for (int j = 0; j < 21; j++) {
        float tl = (j == 20) ? 1.0f : 0.05f * (float)j;
        th[j] = fmaf(tl, range, umin);
    }

    const int nq = n >> 2;
    const float4* rec4 = reinterpret_cast<const float4*>(g_rec);
    #pragma unroll 1
    for (int i = blockIdx.x * P2_T + threadIdx.x; i < nq; i += P2_GRID * P2_T) {
        float4 q = rec4[i];
        hist_one(base, q.x, th);
        hist_one(base, q.y, th);
        hist_one(base, q.z, th);
        hist_one(base, q.w, th);
    }
    if (blockIdx.x == 0 && threadIdx.x == 0) {
        for (int i = nq * 4; i < n; i++) hist_one(base, g_rec[i], th);
    }
    __syncthreads();

    if (threadIdx.x < 88) {
        float sum = 0.0f;
        #pragma unroll 4
        for (int t = 0; t < P2_T; t++) sum += sh[t * P2_S + threadIdx.x];
        if (sum != 0.0f) atomicAdd(&g.hist[threadIdx.x], (double)sum);
    }
    __threadfence();
    __syncthreads();

    if (threadIdx.x == 0) {
        unsigned tk = atomicAdd(&g.ticket, 1u);
        if (tk == P2_GRID - 1) {
            __threadfence();
            float h[88];
            #pragma unroll 4
            for (int i = 0; i < 88; i++) h[i] = (float)g.hist[i];
            float totAU = 0.0f, totIU = 0.0f;
            #pragma unroll
            for (int b = 0; b < 22; b++) { totAU += h[4 * b + 3]; totIU += h[4 * b + 1]; }
            float pAC = 0.0f, pIC = 0.0f, pAU = 0.0f, pIU = 0.0f;
            float auc = 0.0f, prev = 0.0f, prev_tl = 0.0f;
            #pragma unroll 1
            for (int j = 0; j < 21; j++) {
                pAC += h[4 * j + 2];
                pIC += h[4 * j + 0];
                pAU += h[4 * j + 3];
                pIU += h[4 * j + 1];
                float nau = totAU - pAU, niu = totIU - pIU;
                float avu = (pAC + niu) / (pAC + nau + pIC + niu + 1e-10f);
                float tl  = (j == 20) ? 1.0f : 0.05f * (float)j;
                if (j > 0) auc += (avu + prev) * 0.5f * (tl - prev_tl);
                prev = avu; prev_tl = tl;
            }
            double dn = 1.0 / (double)n;
            out[0] = -logf(fmaxf(auc, 1e-10f)) + (float)(g.fo * dn);
            out[1] = (float)(g.ce * dn);
            // ---- self-reset for next graph replay ----
            g.ce = 0.0; g.fo = 0.0;
            g.umaxb = 0u; g.uminneg = 0u;
            #pragma unroll 4
            for (int i = 0; i < 88; i++) g.hist[i] = 0.0;
            __threadfence();
            g.ticket = 0u;
        }
    }
}

// ---------------- launcher --------------------------------------------------
extern "C" void kernel_launch(void* const* d_in, const int* in_sizes, int n_in,
                              void* d_out, int out_size) {
    const float* in0 = (const float*)d_in[0];
    const float* in1 = (const float*)d_in[1];
    int n = in_sizes[0] / CN;
    if (n > NMAX) n = NMAX;

    int npair = n >> 1;
    int nchunk = (npair + CH_PAIRS - 1) / CH_PAIRS;
    int b1 = nchunk < 2048 ? (nchunk > 0 ? nchunk : 1) : 2048;
    pass1<<<b1, P1_T>>>(in0, in1, n);

    pass2<<<P2_GRID, P2_T>>>(n, (float*)d_out);
}

// round 4
// speedup vs baseline: 1.0828x; 1.0828x over previous
#include <cuda_runtime.h>
#include <cuda_fp16.h>

#define NMAX 4194304
#define CN 10

// ---------------- device globals --------------------------------------------
struct GAcc {
    double   ce, fo;
    unsigned umaxb, uminneg;   // max(unc bits), max(~unc bits)  (zero-init neutral)
    unsigned ticket, pad;
    double   hist[88];         // [(b*2+acc)*2 + {0:wc,1:wu}], b in [0,21]
};
static __device__ GAcc g;                            // zero at load; finalizer self-resets
static __device__ __align__(16) float2 g_rec[NMAX];  // .x=unc(sign=!acc) .y=half2(wc,wu)

// ---------------- fast math (FFMA-only, no MUFU) ----------------------------
__device__ __forceinline__ float fast_logf(float a) {
    int   e = (__float_as_int(a) - 0x3f2aaaab) & 0xff800000;
    float m = __int_as_float(__float_as_int(a) - e);
    float i = (float)e * 1.19209290e-7f;
    float f = m - 1.0f;
    float s = f * f;
    float r = fmaf(0.230836749f, f, -0.279208571f);
    float t = fmaf(0.331826031f, f, -0.498910338f);
    r = fmaf(r, s, t);
    r = fmaf(r, s, f);
    r = fmaf(i, 0.693147182f, r);
    return r;
}

__device__ __forceinline__ float fast_expf(float a) {
    float j  = fmaf(1.442695041f, a, 12582912.0f);
    int   ji = __float_as_int(j) - 0x4B400000;
    j = j - 12582912.0f;
    float f = fmaf(j, -0.693145752f, a);
    f = fmaf(j, -1.42860677e-6f, f);
    float r = 1.37805939e-3f;
    r = fmaf(r, f, 8.37312452e-3f);
    r = fmaf(r, f, 4.16695364e-2f);
    r = fmaf(r, f, 1.66665524e-1f);
    r = fmaf(r, f, 4.99999851e-1f);
    r = fmaf(r, f, 1.00000000e+0f);
    r = fmaf(r, f, 1.00000000e+0f);
    return __int_as_float(__float_as_int(r) + (ji << 23));
}

// ---------------- cp.async helpers ------------------------------------------
__device__ __forceinline__ void cp16(unsigned dst, const void* src) {
    asm volatile("cp.async.cg.shared.global [%0], [%1], 16;" :: "r"(dst), "l"(src));
}
__device__ __forceinline__ void cp_commit() { asm volatile("cp.async.commit_group;"); }
__device__ __forceinline__ void cp_wait1()  { asm volatile("cp.async.wait_group 1;"); }
__device__ __forceinline__ void cp_wait0()  { asm volatile("cp.async.wait_group 0;"); }

// ---------------- pass 1 ----------------------------------------------------
#define P1_T   256
#define CHP    256                       // pairs per chunk (== P1_T)
#define CH_F4  (CHP * 5)                 // float4 per tensor per chunk
#define P1_GRID 296
#define P1_SMEM (4 * CH_F4 * 16)         // 2 buffers x 2 tensors = 81920 B

__device__ __forceinline__ float2 proc_sample(const float* p, const float* yy, int label,
                                              float& ceS, float& foS, float& umn, float& umx) {
    float ent = 0.0f, A = 0.0f, B = 0.0f;
    float best = p[0]; int arg = 0;
    #pragma unroll
    for (int c = 0; c < CN; c++) {
        float pk  = p[c];
        float lpe = fast_logf(fmaxf(pk, 1e-10f));             // EPS clamp (entropy)
        float lpf = (pk >= 1e-8f) ? lpe : -18.420680744f;     // FOCAL_EPS clamp
        ent = fmaf(pk, lpe, ent);
        float yl = yy[c] * lpf;
        A += yl;
        B = fmaf(yl, pk, B);
        if (c > 0 && pk > best) { best = pk; arg = c; }       // first-occurrence argmax
    }
    float unc = fmaxf(-ent, 0.0f);
    ceS += -A;
    foS += (B - A);
    umn = fminf(umn, unc);
    umx = fmaxf(umx, unc);

    // soft_T, temp=0.01: hard step with compare-based short circuit
    float e   = unc * 0.43429448190325176f;                   // unc / ln(10)
    float num = e * 0.9f;
    float den = fmaxf((1.0f - e) * 0.1f, 1e-10f);
    float s;
    if (num >= 1.18546522f * den) {            // x >= 17  -> sigmoid rounds to 1.0f
        s = 1.0f;
    } else if (num <= 0.77880078f * den) {     // x <= -25 -> contribution < 1.4e-11
        s = 0.0f;
    } else {
        float x = 100.0f * (fast_logf(fmaxf(num, 1e-37f)) - fast_logf(den));
        s = __fdividef(1.0f, 1.0f + fast_expf(-x));
    }
    float em = fast_expf(-2.0f * unc);
    float t  = __fdividef(1.0f - em, 1.0f + em);              // tanh(unc)

    float wc = (1.0f - s) * (1.0f - t);
    float wu = s * t;
    int   acc = (arg == label);

    float2 rec;
    rec.x = __int_as_float(__float_as_int(unc) | (acc ? 0 : 0x80000000));
    __half2 h = __floats2half2_rn(wc, wu);
    rec.y = __uint_as_float(*reinterpret_cast<unsigned*>(&h));
    return rec;
}

extern __shared__ float4 dbuf[];   // [buf(2)][tensor(2)][CH_F4]

__global__ void __launch_bounds__(P1_T) pass1(const float* __restrict__ in0,
                                              const float* __restrict__ in1, int n) {
    __shared__ int s_label, s_swap;
    __shared__ float rC[P1_T / 32], rF[P1_T / 32], rMn[P1_T / 32], rMx[P1_T / 32];

    if (threadIdx.x == 0) {
        bool onehot = true;
        #pragma unroll
        for (int c = 0; c < CN; c++) { float v = in1[c]; if (v != 0.0f && v != 1.0f) onehot = false; }
        const float* Y = onehot ? in1 : in0;
        s_swap = onehot ? 0 : 1;
        float best = Y[0]; int arg = 0;
        #pragma unroll
        for (int c = 1; c < CN; c++) { float v = Y[c]; if (v > best) { best = v; arg = c; } }
        s_label = arg;
    }
    __syncthreads();
    const int swap = s_swap;
    const int label = s_label;
    const float4* P4 = reinterpret_cast<const float4*>(swap ? in1 : in0);
    const float4* Y4 = reinterpret_cast<const float4*>(swap ? in0 : in1);

    const int npair  = n >> 1;
    const int nF4    = npair * 5;
    const int nchunk = (npair + CHP - 1) / CHP;
    const int t = threadIdx.x;

    unsigned sbase = (unsigned)__cvta_generic_to_shared(dbuf);

    float ceS = 0.0f, foS = 0.0f;
    float umn = 3.402823466e38f, umx = 0.0f;

    // prologue prefetch
    int c0 = blockIdx.x;
    if (c0 < nchunk) {
        unsigned dP = sbase;                         // buf 0, tensor P
        unsigned dY = sbase + CH_F4 * 16;            // buf 0, tensor Y
        #pragma unroll
        for (int r = 0; r < 5; r++) {
            int i = r * P1_T + t;
            int gi = c0 * CH_F4 + i;
            if (gi < nF4) { cp16(dP + i * 16, P4 + gi); cp16(dY + i * 16, Y4 + gi); }
        }
    }
    cp_commit();

    int cur = 0;
    #pragma unroll 1
    for (int c = c0; c < nchunk; c += P1_GRID) {
        int cn = c + P1_GRID;
        int has_next = (cn < nchunk);
        if (has_next) {
            unsigned dP = sbase + (cur ^ 1) * (2 * CH_F4 * 16);
            unsigned dY = dP + CH_F4 * 16;
            #pragma unroll
            for (int r = 0; r < 5; r++) {
                int i = r * P1_T + t;
                int gi = cn * CH_F4 + i;
                if (gi < nF4) { cp16(dP + i * 16, P4 + gi); cp16(dY + i * 16, Y4 + gi); }
            }
        }
        cp_commit();
        if (has_next) cp_wait1(); else cp_wait0();
        __syncthreads();

        int pr = c * CHP + t;
        if (pr < npair) {
            const float4* bP = dbuf + cur * (2 * CH_F4);
            const float4* bY = bP + CH_F4;
            float p[20], y[20];
            #pragma unroll
            for (int j = 0; j < 5; j++) {
                float4 a = bP[t * 5 + j];
                float4 b = bY[t * 5 + j];
                p[4 * j] = a.x; p[4 * j + 1] = a.y; p[4 * j + 2] = a.z; p[4 * j + 3] = a.w;
                y[4 * j] = b.x; y[4 * j + 1] = b.y; y[4 * j + 2] = b.z; y[4 * j + 3] = b.w;
            }
            float2 r0 = proc_sample(p,      y,      label, ceS, foS, umn, umx);
            float2 r1 = proc_sample(p + 10, y + 10, label, ceS, foS, umn, umx);
            float4 o; o.x = r0.x; o.y = r0.y; o.z = r1.x; o.w = r1.y;
            reinterpret_cast<float4*>(g_rec)[pr] = o;
        }
        __syncthreads();
        cur ^= 1;
    }

    // odd-n tail
    if ((n & 1) && blockIdx.x == 0 && threadIdx.x == 0) {
        int i = n - 1;
        const float* P = swap ? in1 : in0;
        const float* Y = swap ? in0 : in1;
        float v[CN], w[CN];
        #pragma unroll
        for (int c = 0; c < CN; c++) { v[c] = P[(size_t)i * CN + c]; w[c] = Y[(size_t)i * CN + c]; }
        g_rec[i] = proc_sample(v, w, label, ceS, foS, umn, umx);
    }

    #pragma unroll
    for (int o = 16; o; o >>= 1) {
        ceS += __shfl_xor_sync(0xffffffffu, ceS, o);
        foS += __shfl_xor_sync(0xffffffffu, foS, o);
        umn = fminf(umn, __shfl_xor_sync(0xffffffffu, umn, o));
        umx = fmaxf(umx, __shfl_xor_sync(0xffffffffu, umx, o));
    }
    int wid = threadIdx.x >> 5, lid = threadIdx.x & 31;
    if (lid == 0) { rC[wid] = ceS; rF[wid] = foS; rMn[wid] = umn; rMx[wid] = umx; }
    __syncthreads();
    if (threadIdx.x == 0) {
        float cc = rC[0], f = rF[0], mn = rMn[0], mx = rMx[0];
        #pragma unroll
        for (int q = 1; q < P1_T / 32; q++) {
            cc += rC[q]; f += rF[q]; mn = fminf(mn, rMn[q]); mx = fmaxf(mx, rMx[q]);
        }
        atomicAdd(&g.ce, (double)cc);
        atomicAdd(&g.fo, (double)f);
        atomicMax(&g.umaxb, __float_as_uint(mx));
        atomicMax(&g.uminneg, ~__float_as_uint(mn));
    }
}

// ---------------- pass 2: half2 hist, arithmetic bin, finalize --------------
#define P2_T 128
#define P2_S 45          // 44 half2 entries + 1 pad word
#define P2_GRID 1184

__device__ __forceinline__ void hist_one(unsigned* base, float ux, float wbits,
                                         float umin, float range, float istep, float noff) {
    int   bits = __float_as_int(ux);
    int   acc  = (bits < 0) ? 0 : 1;
    float unc  = fabsf(ux);

    // arithmetic bin + 3 exact-compare fixup (== 21-compare loop exactly)
    float u  = fmaf(unc, istep, noff);
    float kf = fminf(fmaxf(floorf(u), 1.0f), 19.0f);
    int   k  = (int)kf;
    float s5 = 0.05f * range;
    float thm = fmaf(kf - 1.0f, s5, umin);
    float th0 = fmaf(kf,        s5, umin);
    float thp = fmaf(kf + 1.0f, s5, umin);
    int b = (k - 1) + (unc > thm) + (unc > th0) + (unc > thp);   // in [0,21]

    unsigned idx = (unsigned)(b * 2 + acc);
    unsigned old = base[idx];
    __half2 h  = *reinterpret_cast<__half2*>(&old);
    unsigned wv = __float_as_uint(wbits);
    __half2 w  = *reinterpret_cast<__half2*>(&wv);
    h = __hadd2(h, w);
    base[idx] = *reinterpret_cast<unsigned*>(&h);
}

__global__ void __launch_bounds__(P2_T) pass2(int n, float* __restrict__ out) {
    __shared__ unsigned sh[P2_T * P2_S];
    unsigned* base = sh + threadIdx.x * P2_S;
    #pragma unroll
    for (int k = 0; k < P2_S; k++) base[k] = 0u;
    __syncthreads();

    float umin  = __uint_as_float(~g.uminneg);
    float umax  = __uint_as_float(g.umaxb);
    float range = umax - umin;
    float istep = (range > 0.0f) ? __fdividef(20.0f, range) : 0.0f;
    float noff  = -umin * istep;

    const int npair = n >> 1;
    const float4* rec4 = reinterpret_cast<const float4*>(g_rec);
    #pragma unroll 1
    for (int i = blockIdx.x * P2_T + threadIdx.x; i < npair; i += P2_GRID * P2_T) {
        float4 q = rec4[i];
        hist_one(base, q.x, q.y, umin, range, istep, noff);
        hist_one(base, q.z, q.w, umin, range, istep, noff);
    }
    if ((n & 1) && blockIdx.x == 0 && threadIdx.x == 0) {
        float2 r = g_rec[n - 1];
        hist_one(base, r.x, r.y, umin, range, istep, noff);
    }
    __syncthreads();

    if (threadIdx.x < 44) {
        float swc = 0.0f, swu = 0.0f;
        #pragma unroll 4
        for (int t = 0; t < P2_T; t++) {
            unsigned v = sh[t * P2_S + threadIdx.x];
            __half2 h = *reinterpret_cast<__half2*>(&v);
            swc += __low2float(h);
            swu += __high2float(h);
        }
        if (swc != 0.0f) atomicAdd(&g.hist[threadIdx.x * 2 + 0], (double)swc);
        if (swu != 0.0f) atomicAdd(&g.hist[threadIdx.x * 2 + 1], (double)swu);
    }
    __threadfence();
    __syncthreads();

    if (threadIdx.x == 0) {
        unsigned tk = atomicAdd(&g.ticket, 1u);
        if (tk == P2_GRID - 1) {
            __threadfence();
            float h[88];
            #pragma unroll 4
            for (int i = 0; i < 88; i++) h[i] = (float)g.hist[i];
            float totAU = 0.0f, totIU = 0.0f;
            #pragma unroll
            for (int b = 0; b < 22; b++) { totAU += h[4 * b + 3]; totIU += h[4 * b + 1]; }
            float pAC = 0.0f, pIC = 0.0f, pAU = 0.0f, pIU = 0.0f;
            float auc = 0.0f, prev = 0.0f, prev_tl = 0.0f;
            #pragma unroll 1
            for (int j = 0; j < 21; j++) {
                pAC += h[4 * j + 2];
                pIC += h[4 * j + 0];
                pAU += h[4 * j + 3];
                pIU += h[4 * j + 1];
                float nau = totAU - pAU, niu = totIU - pIU;
                float avu = (pAC + niu) / (pAC + nau + pIC + niu + 1e-10f);
                float tl  = (j == 20) ? 1.0f : 0.05f * (float)j;
                if (j > 0) auc += (avu + prev) * 0.5f * (tl - prev_tl);
                prev = avu; prev_tl = tl;
            }
            double dn = 1.0 / (double)n;
            out[0] = -logf(fmaxf(auc, 1e-10f)) + (float)(g.fo * dn);
            out[1] = (float)(g.ce * dn);
            // self-reset for next graph replay
            g.ce = 0.0; g.fo = 0.0;
            g.umaxb = 0u; g.uminneg = 0u;
            #pragma unroll 4
            for (int i = 0; i < 88; i++) g.hist[i] = 0.0;
            __threadfence();
            g.ticket = 0u;
        }
    }
}

// ---------------- launcher --------------------------------------------------
extern "C" void kernel_launch(void* const* d_in, const int* in_sizes, int n_in,
                              void* d_out, int out_size) {
    const float* in0 = (const float*)d_in[0];
    const float* in1 = (const float*)d_in[1];
    int n = in_sizes[0] / CN;
    if (n > NMAX) n = NMAX;

    cudaFuncSetAttribute(pass1, cudaFuncAttributeMaxDynamicSharedMemorySize, P1_SMEM);

    pass1<<<P1_GRID, P1_T, P1_SMEM>>>(in0, in1, n);
    pass2<<<P2_GRID, P2_T>>>(n, (float*)d_out);
}

// round 5
// speedup vs baseline: 1.2532x; 1.1574x over previous
#include <cuda_runtime.h>
#include <cuda_fp16.h>

#define NMAX 4194304
#define CN 10

// ---------------- device globals --------------------------------------------
struct GAcc {
    double   ce, fo;
    unsigned umaxb, uminneg;   // max(unc bits), max(~unc bits)  (zero-init neutral)
    unsigned ticket, pad;
    float    histF[88];        // [(b*2+acc)*2 + {0:wc,1:wu}], b in [0,21]
};
static __device__ GAcc g;                            // zero at load; finalizer self-resets
static __device__ __align__(16) float2 g_rec[NMAX];  // .x=unc(sign=!acc) .y=half2(wc,wu)

// ---------------- fast math (FFMA-only, no MUFU) ----------------------------
__device__ __forceinline__ float fast_logf(float a) {
    int   e = (__float_as_int(a) - 0x3f2aaaab) & 0xff800000;
    float m = __int_as_float(__float_as_int(a) - e);
    float i = (float)e * 1.19209290e-7f;
    float f = m - 1.0f;
    float s = f * f;
    float r = fmaf(0.230836749f, f, -0.279208571f);
    float t = fmaf(0.331826031f, f, -0.498910338f);
    r = fmaf(r, s, t);
    r = fmaf(r, s, f);
    r = fmaf(i, 0.693147182f, r);
    return r;
}

__device__ __forceinline__ float fast_expf(float a) {
    float j  = fmaf(1.442695041f, a, 12582912.0f);
    int   ji = __float_as_int(j) - 0x4B400000;
    j = j - 12582912.0f;
    float f = fmaf(j, -0.693145752f, a);
    f = fmaf(j, -1.42860677e-6f, f);
    float r = 1.37805939e-3f;
    r = fmaf(r, f, 8.37312452e-3f);
    r = fmaf(r, f, 4.16695364e-2f);
    r = fmaf(r, f, 1.66665524e-1f);
    r = fmaf(r, f, 4.99999851e-1f);
    r = fmaf(r, f, 1.00000000e+0f);
    r = fmaf(r, f, 1.00000000e+0f);
    return __int_as_float(__float_as_int(r) + (ji << 23));
}

// ---------------- cp.async / cache-policy helpers ---------------------------
__device__ __forceinline__ unsigned long long pol_first() {
    unsigned long long p;
    asm("createpolicy.fractional.L2::evict_first.b64 %0, 1.0;" : "=l"(p));
    return p;
}
__device__ __forceinline__ unsigned long long pol_last() {
    unsigned long long p;
    asm("createpolicy.fractional.L2::evict_last.b64 %0, 1.0;" : "=l"(p));
    return p;
}
__device__ __forceinline__ void cp16p(unsigned dst, const void* src, unsigned long long pol) {
    asm volatile("cp.async.cg.shared.global.L2::cache_hint [%0], [%1], 16, %2;"
                 :: "r"(dst), "l"(src), "l"(pol));
}
__device__ __forceinline__ void st4_last(void* p, float4 v, unsigned long long pol) {
    asm volatile("st.global.L2::cache_hint.v4.f32 [%0], {%1,%2,%3,%4}, %5;"
                 :: "l"(p), "f"(v.x), "f"(v.y), "f"(v.z), "f"(v.w), "l"(pol) : "memory");
}
__device__ __forceinline__ void cp_commit() { asm volatile("cp.async.commit_group;"); }
__device__ __forceinline__ void cp_wait1()  { asm volatile("cp.async.wait_group 1;"); }
__device__ __forceinline__ void cp_wait0()  { asm volatile("cp.async.wait_group 0;"); }

// ---------------- pass 1 ----------------------------------------------------
#define P1_T   256
#define CHP    256                       // pairs per chunk (== P1_T)
#define CH_F4  (CHP * 5)                 // float4 per tensor per chunk
#define P1_GRID 296
#define P1_SMEM (4 * CH_F4 * 16)         // 2 buffers x 2 tensors = 81920 B

__device__ __forceinline__ float2 proc_sample(const float* p, const float* yy, int label,
                                              float& ceS, float& foS, float& umn, float& umx) {
    float ent = 0.0f, A = 0.0f, B = 0.0f;
    float best = p[0]; int arg = 0;
    #pragma unroll
    for (int c = 0; c < CN; c++) {
        float pk  = p[c];
        float lpe = fast_logf(fmaxf(pk, 1e-10f));             // EPS clamp (entropy)
        float lpf = (pk >= 1e-8f) ? lpe : -18.420680744f;     // FOCAL_EPS clamp
        ent = fmaf(pk, lpe, ent);
        float yl = yy[c] * lpf;
        A += yl;
        B = fmaf(yl, pk, B);
        if (c > 0 && pk > best) { best = pk; arg = c; }       // first-occurrence argmax
    }
    float unc = fmaxf(-ent, 0.0f);
    ceS += -A;
    foS += (B - A);
    umn = fminf(umn, unc);
    umx = fmaxf(umx, unc);

    // soft_T, temp=0.01: hard step with compare-based short circuit
    float e   = unc * 0.43429448190325176f;                   // unc / ln(10)
    float num = e * 0.9f;
    float den = fmaxf((1.0f - e) * 0.1f, 1e-10f);
    float s;
    if (num >= 1.18546522f * den) {            // x >= 17  -> sigmoid rounds to 1.0f
        s = 1.0f;
    } else if (num <= 0.77880078f * den) {     // x <= -25 -> contribution < 1.4e-11
        s = 0.0f;
    } else {
        float x = 100.0f * (fast_logf(fmaxf(num, 1e-37f)) - fast_logf(den));
        s = __fdividef(1.0f, 1.0f + fast_expf(-x));
    }
    float em = fast_expf(-2.0f * unc);
    float t  = __fdividef(1.0f - em, 1.0f + em);              // tanh(unc)

    float wc = (1.0f - s) * (1.0f - t);
    float wu = s * t;
    int   acc = (arg == label);

    float2 rec;
    rec.x = __int_as_float(__float_as_int(unc) | (acc ? 0 : 0x80000000));
    __half2 h = __floats2half2_rn(wc, wu);
    rec.y = __uint_as_float(*reinterpret_cast<unsigned*>(&h));
    return rec;
}

extern __shared__ float4 dbuf[];   // [buf(2)][tensor(2)][CH_F4]

__global__ void __launch_bounds__(P1_T) pass1(const float* __restrict__ in0,
                                              const float* __restrict__ in1, int n) {
    __shared__ int s_label, s_swap;
    __shared__ float rC[P1_T / 32], rF[P1_T / 32], rMn[P1_T / 32], rMx[P1_T / 32];

    if (threadIdx.x == 0) {
        bool onehot = true;
        #pragma unroll
        for (int c = 0; c < CN; c++) { float v = in1[c]; if (v != 0.0f && v != 1.0f) onehot = false; }
        const float* Y = onehot ? in1 : in0;
        s_swap = onehot ? 0 : 1;
        float best = Y[0]; int arg = 0;
        #pragma unroll
        for (int c = 1; c < CN; c++) { float v = Y[c]; if (v > best) { best = v; arg = c; } }
        s_label = arg;
    }
    __syncthreads();
    const int swap = s_swap;
    const int label = s_label;
    const float4* P4 = reinterpret_cast<const float4*>(swap ? in1 : in0);
    const float4* Y4 = reinterpret_cast<const float4*>(swap ? in0 : in1);

    const unsigned long long pfirst = pol_first();
    const unsigned long long plast  = pol_last();

    const int npair  = n >> 1;
    const int nF4    = npair * 5;
    const int nchunk = (npair + CHP - 1) / CHP;
    const int t = threadIdx.x;

    unsigned sbase = (unsigned)__cvta_generic_to_shared(dbuf);

    float ceS = 0.0f, foS = 0.0f;
    float umn = 3.402823466e38f, umx = 0.0f;

    // prologue prefetch
    int c0 = blockIdx.x;
    if (c0 < nchunk) {
        unsigned dP = sbase;                         // buf 0, tensor P
        unsigned dY = sbase + CH_F4 * 16;            // buf 0, tensor Y
        #pragma unroll
        for (int r = 0; r < 5; r++) {
            int i = r * P1_T + t;
            int gi = c0 * CH_F4 + i;
            if (gi < nF4) { cp16p(dP + i * 16, P4 + gi, pfirst); cp16p(dY + i * 16, Y4 + gi, pfirst); }
        }
    }
    cp_commit();

    int cur = 0;
    #pragma unroll 1
    for (int c = c0; c < nchunk; c += P1_GRID) {
        int cn = c + P1_GRID;
        int has_next = (cn < nchunk);
        if (has_next) {
            unsigned dP = sbase + (cur ^ 1) * (2 * CH_F4 * 16);
            unsigned dY = dP + CH_F4 * 16;
            #pragma unroll
            for (int r = 0; r < 5; r++) {
                int i = r * P1_T + t;
                int gi = cn * CH_F4 + i;
                if (gi < nF4) { cp16p(dP + i * 16, P4 + gi, pfirst); cp16p(dY + i * 16, Y4 + gi, pfirst); }
            }
        }
        cp_commit();
        if (has_next) cp_wait1(); else cp_wait0();
        __syncthreads();

        int pr = c * CHP + t;
        if (pr < npair) {
            const float4* bP = dbuf + cur * (2 * CH_F4);
            const float4* bY = bP + CH_F4;
            float p[20], y[20];
            #pragma unroll
            for (int j = 0; j < 5; j++) {
                float4 a = bP[t * 5 + j];
                float4 b = bY[t * 5 + j];
                p[4 * j] = a.x; p[4 * j + 1] = a.y; p[4 * j + 2] = a.z; p[4 * j + 3] = a.w;
                y[4 * j] = b.x; y[4 * j + 1] = b.y; y[4 * j + 2] = b.z; y[4 * j + 3] = b.w;
            }
            float2 r0 = proc_sample(p,      y,      label, ceS, foS, umn, umx);
            float2 r1 = proc_sample(p + 10, y + 10, label, ceS, foS, umn, umx);
            float4 o; o.x = r0.x; o.y = r0.y; o.z = r1.x; o.w = r1.y;
            st4_last(reinterpret_cast<float4*>(g_rec) + pr, o, plast);   // keep in L2
        }
        __syncthreads();
        cur ^= 1;
    }

    // odd-n tail
    if ((n & 1) && blockIdx.x == 0 && threadIdx.x == 0) {
        int i = n - 1;
        const float* P = swap ? in1 : in0;
        const float* Y = swap ? in0 : in1;
        float v[CN], w[CN];
        #pragma unroll
        for (int c = 0; c < CN; c++) { v[c] = P[(size_t)i * CN + c]; w[c] = Y[(size_t)i * CN + c]; }
        g_rec[i] = proc_sample(v, w, label, ceS, foS, umn, umx);
    }

    #pragma unroll
    for (int o = 16; o; o >>= 1) {
        ceS += __shfl_xor_sync(0xffffffffu, ceS, o);
        foS += __shfl_xor_sync(0xffffffffu, foS, o);
        umn = fminf(umn, __shfl_xor_sync(0xffffffffu, umn, o));
        umx = fmaxf(umx, __shfl_xor_sync(0xffffffffu, umx, o));
    }
    int wid = threadIdx.x >> 5, lid = threadIdx.x & 31;
    if (lid == 0) { rC[wid] = ceS; rF[wid] = foS; rMn[wid] = umn; rMx[wid] = umx; }
    __syncthreads();
    if (threadIdx.x == 0) {
        float cc = rC[0], f = rF[0], mn = rMn[0], mx = rMx[0];
        #pragma unroll
        for (int q = 1; q < P1_T / 32; q++) {
            cc += rC[q]; f += rF[q]; mn = fminf(mn, rMn[q]); mx = fmaxf(mx, rMx[q]);
        }
        atomicAdd(&g.ce, (double)cc);
        atomicAdd(&g.fo, (double)f);
        atomicMax(&g.umaxb, __float_as_uint(mx));
        atomicMax(&g.uminneg, ~__float_as_uint(mn));
    }
}

// ---------------- pass 2: half2 hist, MLP=4, float RED tail -----------------
#define P2_T 128
#define P2_S 45          // 44 half2 entries + 1 pad word
#define P2_GRID 1184

__device__ __forceinline__ void hist_one(unsigned* base, float ux, float wbits,
                                         float umin, float range, float istep, float noff) {
    int   bits = __float_as_int(ux);
    int   acc  = (bits < 0) ? 0 : 1;
    float unc  = fabsf(ux);

    // arithmetic bin + 3 exact-compare fixup (== 21-compare loop exactly)
    float u  = fmaf(unc, istep, noff);
    float kf = fminf(fmaxf(floorf(u), 1.0f), 19.0f);
    int   k  = (int)kf;
    float s5 = 0.05f * range;
    float thm = fmaf(kf - 1.0f, s5, umin);
    float th0 = fmaf(kf,        s5, umin);
    float thp = fmaf(kf + 1.0f, s5, umin);
    int b = (k - 1) + (unc > thm) + (unc > th0) + (unc > thp);   // in [0,21]

    unsigned idx = (unsigned)(b * 2 + acc);
    unsigned old = base[idx];
    __half2 h  = *reinterpret_cast<__half2*>(&old);
    unsigned wv = __float_as_uint(wbits);
    __half2 w  = *reinterpret_cast<__half2*>(&wv);
    h = __hadd2(h, w);
    base[idx] = *reinterpret_cast<unsigned*>(&h);
}

__global__ void __launch_bounds__(P2_T) pass2(int n, float* __restrict__ out) {
    __shared__ unsigned sh[P2_T * P2_S];
    unsigned* base = sh + threadIdx.x * P2_S;
    #pragma unroll
    for (int k = 0; k < P2_S; k++) base[k] = 0u;
    __syncthreads();

    float umin  = __uint_as_float(~g.uminneg);
    float umax  = __uint_as_float(g.umaxb);
    float range = umax - umin;
    float istep = (range > 0.0f) ? __fdividef(20.0f, range) : 0.0f;
    float noff  = -umin * istep;

    const int npair = n >> 1;
    const int S = P2_GRID * P2_T;
    const float4* rec4 = reinterpret_cast<const float4*>(g_rec);

    int i = blockIdx.x * P2_T + threadIdx.x;
    #pragma unroll 1
    for (; i + 3 * S < npair; i += 4 * S) {
        float4 a = rec4[i];
        float4 b = rec4[i + S];
        float4 c = rec4[i + 2 * S];
        float4 d = rec4[i + 3 * S];
        hist_one(base, a.x, a.y, umin, range, istep, noff);
        hist_one(base, a.z, a.w, umin, range, istep, noff);
        hist_one(base, b.x, b.y, umin, range, istep, noff);
        hist_one(base, b.z, b.w, umin, range, istep, noff);
        hist_one(base, c.x, c.y, umin, range, istep, noff);
        hist_one(base, c.z, c.w, umin, range, istep, noff);
        hist_one(base, d.x, d.y, umin, range, istep, noff);
        hist_one(base, d.z, d.w, umin, range, istep, noff);
    }
    #pragma unroll 1
    for (; i < npair; i += S) {
        float4 a = rec4[i];
        hist_one(base, a.x, a.y, umin, range, istep, noff);
        hist_one(base, a.z, a.w, umin, range, istep, noff);
    }
    if ((n & 1) && blockIdx.x == 0 && threadIdx.x == 0) {
        float2 r = g_rec[n - 1];
        hist_one(base, r.x, r.y, umin, range, istep, noff);
    }
    __syncthreads();

    if (threadIdx.x < 44) {
        float swc = 0.0f, swu = 0.0f;
        #pragma unroll 4
        for (int t = 0; t < P2_T; t++) {
            unsigned v = sh[t * P2_S + threadIdx.x];
            __half2 h = *reinterpret_cast<__half2*>(&v);
            swc += __low2float(h);
            swu += __high2float(h);
        }
        if (swc != 0.0f) atomicAdd(&g.histF[threadIdx.x * 2 + 0], swc);   // RED.F32
        if (swu != 0.0f) atomicAdd(&g.histF[threadIdx.x * 2 + 1], swu);
    }
    __threadfence();
    __syncthreads();

    if (threadIdx.x == 0) {
        unsigned tk = atomicAdd(&g.ticket, 1u);
        if (tk == P2_GRID - 1) {
            __threadfence();
            float h[88];
            #pragma unroll 4
            for (int i2 = 0; i2 < 88; i2++) h[i2] = g.histF[i2];
            float totAU = 0.0f, totIU = 0.0f;
            #pragma unroll
            for (int b = 0; b < 22; b++) { totAU += h[4 * b + 3]; totIU += h[4 * b + 1]; }
            float pAC = 0.0f, pIC = 0.0f, pAU = 0.0f, pIU = 0.0f;
            float auc = 0.0f, prev = 0.0f, prev_tl = 0.0f;
            #pragma unroll 1
            for (int j = 0; j < 21; j++) {
                pAC += h[4 * j + 2];
                pIC += h[4 * j + 0];
                pAU += h[4 * j + 3];
                pIU += h[4 * j + 1];
                float nau = totAU - pAU, niu = totIU - pIU;
                float avu = (pAC + niu) / (pAC + nau + pIC + niu + 1e-10f);
                float tl  = (j == 20) ? 1.0f : 0.05f * (float)j;
                if (j > 0) auc += (avu + prev) * 0.5f * (tl - prev_tl);
                prev = avu; prev_tl = tl;
            }
            double dn = 1.0 / (double)n;
            out[0] = -logf(fmaxf(auc, 1e-10f)) + (float)(g.fo * dn);
            out[1] = (float)(g.ce * dn);
            // self-reset for next graph replay
            g.ce = 0.0; g.fo = 0.0;
            g.umaxb = 0u; g.uminneg = 0u;
            #pragma unroll 4
            for (int i2 = 0; i2 < 88; i2++) g.histF[i2] = 0.0f;
            __threadfence();
            g.ticket = 0u;
        }
    }
}

// ---------------- launcher --------------------------------------------------
extern "C" void kernel_launch(void* const* d_in, const int* in_sizes, int n_in,
                              void* d_out, int out_size) {
    const float* in0 = (const float*)d_in[0];
    const float* in1 = (const float*)d_in[1];
    int n = in_sizes[0] / CN;
    if (n > NMAX) n = NMAX;

    cudaFuncSetAttribute(pass1, cudaFuncAttributeMaxDynamicSharedMemorySize, P1_SMEM);

    pass1<<<P1_GRID, P1_T, P1_SMEM>>>(in0, in1, n);
    pass2<<<P2_GRID, P2_T>>>(n, (float*)d_out);
}